// round 6
// baseline (speedup 1.0000x reference)
#include <cuda_runtime.h>
#include <math.h>

#define BB 32
#define TL 256
#define DL 512
#define HH 512
#define VV 2000
#define MM 256
#define G4 2048
#define XD 2512
#define CATD 1024
#define NSTEP 100
#define NT 256

#define S_WIH0 20   // K=2512 split into chunks of 128
#define S_WHH  4    // K=512 chunks of 128
#define S_P0   24   // 20 + 4
#define S_P1   8    // 4 (Whh1) + 4 (Wih1)
#define S_PL   8    // 4 (h1 half) + 4 (ctx half)
#define LROWS  2048 // padded logits rows

// ---------------- persistent device state ----------------
__device__ float g_x[BB * XD];
__device__ float g_h0[BB * HH], g_c0[BB * HH], g_h1[BB * HH], g_c1[BB * HH];
__device__ float g_cat[BB * CATD];
__device__ float g_p0[(size_t)S_P0 * G4 * BB];
__device__ float g_p1[(size_t)S_P1 * G4 * BB];
__device__ float g_pl[(size_t)S_PL * LROWS * BB];
__device__ float g_clisT[(size_t)BB * MM * TL];
__device__ unsigned g_barArr = 0;
__device__ unsigned g_barGen = 0;

__device__ __forceinline__ float sigmoidf_(float x) { return 1.f / (1.f + expf(-x)); }

// ---------------- grid barrier (all blocks resident) ----------------
__device__ __forceinline__ void gsync(unsigned& gen_next) {
    __threadfence();                 // publish my writes (gpu scope)
    __syncthreads();
    if (threadIdx.x == 0) {
        if (atomicAdd(&g_barArr, 1u) == gridDim.x - 1) {
            g_barArr = 0;
            __threadfence();
            atomicAdd(&g_barGen, 1u);
        } else {
            while (atomicAdd(&g_barGen, 0u) < gen_next) __nanosleep(40);
        }
        gen_next++;
    }
    __syncthreads();
    __threadfence();                 // acquire: flush L1 for fresh reads
}

// ---------------- GEMM partial task: 128 rows x 32 batch, K range [k0,k1) ----
// out[r*32 + b] = sum_{k in [k0,k1)} W[r][k] * X[b][k]
__device__ void gemm_task(const float* __restrict__ W, int ldw, int mrows,
                          const float* __restrict__ X, int ldx,
                          int rbase, int k0, int k1,
                          float* __restrict__ out, float* sm) {
    float* Ws = sm;                 // 128*33
    float* Xs = sm + 128 * 33;      // 32*33
    const int tid = threadIdx.x;
    const int rowg = tid >> 3, bg = tid & 7;
    float acc[4][4] = {};
    for (int kc = k0; kc < k1; kc += 32) {
#pragma unroll
        for (int i = 0; i < 16; i++) {
            int lin = tid + i * NT;
            int row = lin >> 5, kk = lin & 31;
            int r = rbase + row, k = kc + kk;
            Ws[row * 33 + kk] = (k < k1 && r < mrows) ? W[(size_t)r * ldw + k] : 0.f;
        }
#pragma unroll
        for (int i = 0; i < 4; i++) {
            int lin = tid + i * NT;
            int bb = lin >> 5, kk = lin & 31;
            int k = kc + kk;
            Xs[bb * 33 + kk] = (k < k1) ? __ldcg(&X[(size_t)bb * ldx + k]) : 0.f;
        }
        __syncthreads();
#pragma unroll 8
        for (int kk = 0; kk < 32; kk++) {
            float wv[4], xv[4];
#pragma unroll
            for (int i = 0; i < 4; i++) wv[i] = Ws[(rowg * 4 + i) * 33 + kk];
#pragma unroll
            for (int j = 0; j < 4; j++) xv[j] = Xs[(bg * 4 + j) * 33 + kk];
#pragma unroll
            for (int i = 0; i < 4; i++)
#pragma unroll
                for (int j = 0; j < 4; j++) acc[i][j] = fmaf(wv[i], xv[j], acc[i][j]);
        }
        __syncthreads();
    }
#pragma unroll
    for (int i = 0; i < 4; i++) {
        int r = rbase + rowg * 4 + i;
        if (r < mrows)
#pragma unroll
            for (int j = 0; j < 4; j++)
                out[(size_t)r * BB + bg * 4 + j] = acc[i][j];
    }
}

// ---------------- LSTM cell: reduce partial slots + activations --------------
__device__ void cell_phase(const float* __restrict__ P, int nslots,
                           const float* __restrict__ bih, const float* __restrict__ bhh,
                           float* __restrict__ h, float* __restrict__ c,
                           float* __restrict__ hcopy) {
    int idx = blockIdx.x * NT + threadIdx.x;
    if (idx < BB * HH) {
        int b = idx & 31, j = idx >> 5;
        float g[4];
#pragma unroll
        for (int gi = 0; gi < 4; gi++) {
            int r = gi * HH + j;
            float v = bih[r] + bhh[r];
            const float* p = P + (size_t)r * BB + b;
#pragma unroll 4
            for (int s = 0; s < nslots; s++) v += __ldcg(&p[(size_t)s * G4 * BB]);
            g[gi] = v;
        }
        float ig = sigmoidf_(g[0]);
        float fg = sigmoidf_(g[1]);
        float gg = tanhf(g[2]);
        float og = sigmoidf_(g[3]);
        float cn = fg * __ldcg(&c[b * HH + j]) + ig * gg;
        float hn = og * tanhf(cn);
        c[b * HH + j] = cn;
        h[b * HH + j] = hn;
        if (hcopy) hcopy[b * CATD + j] = hn;
    }
}

// ---------------- attention for one batch (block) ----------------------------
__device__ void attn_phase(int b, const float* __restrict__ lis,
                           const float* __restrict__ Wphi, const float* __restrict__ bphi,
                           float* __restrict__ attn_out, float* sm) {
    float* h1s = sm;            // 512
    float* cd  = sm + 512;      // 256
    float* av  = sm + 768;      // 256
    float* rb  = sm + 1024;     // 256
    int tid = threadIdx.x;
    for (int i = tid; i < HH; i += NT) h1s[i] = __ldcg(&g_h1[b * HH + i]);
    __syncthreads();
    int warp = tid >> 5, lane = tid & 31;
    for (int m = warp; m < MM; m += 8) {
        const float* w = Wphi + (size_t)m * HH;
        float p = 0.f;
#pragma unroll 4
        for (int k = lane; k < HH; k += 32) p = fmaf(w[k], h1s[k], p);
#pragma unroll
        for (int o = 16; o; o >>= 1) p += __shfl_down_sync(0xffffffffu, p, o);
        if (lane == 0) cd[m] = fmaxf(p + bphi[m], 0.f);
    }
    __syncthreads();
    // energy for t = tid
    const float* cl = g_clisT + (size_t)b * MM * TL + tid;
    float e = 0.f;
#pragma unroll 8
    for (int m = 0; m < MM; m++) e = fmaf(cd[m], cl[(size_t)m * TL], e);
    rb[tid] = e; __syncthreads();
    for (int o = 128; o > 0; o >>= 1) { if (tid < o) rb[tid] = fmaxf(rb[tid], rb[tid + o]); __syncthreads(); }
    float mx = rb[0]; __syncthreads();
    float p = expf(e - mx);
    rb[tid] = p; __syncthreads();
    for (int o = 128; o > 0; o >>= 1) { if (tid < o) rb[tid] += rb[tid + o]; __syncthreads(); }
    float a = p / rb[0];
    av[tid] = a;
    attn_out[tid] = a;
    __syncthreads();
    const float* lb = lis + (size_t)b * TL * DL;
#pragma unroll
    for (int dd = 0; dd < 2; dd++) {
        int d = tid + dd * NT;
        float cx = 0.f;
#pragma unroll 4
        for (int t = 0; t < TL; t++) cx = fmaf(av[t], lb[(size_t)t * DL + d], cx);
        g_cat[b * CATD + HH + d] = cx;
        g_x[(size_t)b * XD + VV + d] = cx;
    }
}

// ---------------- log-softmax + feedback for one batch -----------------------
__device__ void lsm_phase(int b, const float* __restrict__ bc,
                          float* __restrict__ preds_out, float* sm) {
    float* lg = sm;             // 2048
    float* rb = sm + 2048;      // 256
    int tid = threadIdx.x;
    float lmax = -1e30f;
    for (int v = tid; v < VV; v += NT) {
        float x = bc[v];
        const float* p = g_pl + (size_t)v * BB + b;
#pragma unroll
        for (int s = 0; s < S_PL; s++) x += __ldcg(&p[(size_t)s * LROWS * BB]);
        lg[v] = x;
        lmax = fmaxf(lmax, x);
    }
    rb[tid] = lmax; __syncthreads();
    for (int o = 128; o > 0; o >>= 1) { if (tid < o) rb[tid] = fmaxf(rb[tid], rb[tid + o]); __syncthreads(); }
    float mx = rb[0]; __syncthreads();
    float s = 0.f;
    for (int v = tid; v < VV; v += NT) s += expf(lg[v] - mx);
    rb[tid] = s; __syncthreads();
    for (int o = 128; o > 0; o >>= 1) { if (tid < o) rb[tid] += rb[tid + o]; __syncthreads(); }
    float lse = mx + logf(rb[0]);
    for (int v = tid; v < VV; v += NT) {
        float r = lg[v] - lse;
        preds_out[(size_t)b * VV + v] = r;
        g_x[(size_t)b * XD + v] = r;
    }
}

// ---------------- one-time psi: clisT[b][m][t] --------------------------------
__device__ void psi_task(int task, const float* __restrict__ lis,
                         const float* __restrict__ Wpsi, const float* __restrict__ bpsi,
                         float* sm) {
    int b = task >> 4;
    int rem = task & 15;
    int mb = rem >> 1, tb = rem & 1;      // 8 m-tiles of 32, 2 t-tiles of 128
    float* Ws = sm;                       // 32*33
    float* Ls = sm + 32 * 33;             // 128*33
    int tid = threadIdx.x;
    int mg = tid >> 5, tg = tid & 31;
    float acc[4][4] = {};
    const float* lb = lis + (size_t)b * TL * DL;
    for (int kc = 0; kc < DL; kc += 32) {
#pragma unroll
        for (int i = 0; i < 4; i++) {
            int lin = tid + i * NT;
            int row = lin >> 5, kk = lin & 31;
            Ws[row * 33 + kk] = Wpsi[(size_t)(mb * 32 + row) * DL + kc + kk];
        }
#pragma unroll
        for (int i = 0; i < 16; i++) {
            int lin = tid + i * NT;
            int row = lin >> 5, kk = lin & 31;
            Ls[row * 33 + kk] = lb[(size_t)(tb * 128 + row) * DL + kc + kk];
        }
        __syncthreads();
#pragma unroll 8
        for (int kk = 0; kk < 32; kk++) {
            float wv[4], lv[4];
#pragma unroll
            for (int i = 0; i < 4; i++) wv[i] = Ws[(mg * 4 + i) * 33 + kk];
#pragma unroll
            for (int j = 0; j < 4; j++) lv[j] = Ls[(tg * 4 + j) * 33 + kk];
#pragma unroll
            for (int i = 0; i < 4; i++)
#pragma unroll
                for (int j = 0; j < 4; j++) acc[i][j] = fmaf(wv[i], lv[j], acc[i][j]);
        }
        __syncthreads();
    }
#pragma unroll
    for (int i = 0; i < 4; i++) {
        int m = mb * 32 + mg * 4 + i;
        float bias = bpsi[m];
#pragma unroll
        for (int j = 0; j < 4; j++) {
            int t = tb * 128 + tg * 4 + j;
            g_clisT[((size_t)b * MM + m) * TL + t] = fmaxf(acc[i][j] + bias, 0.f);
        }
    }
}

// ---------------- persistent megakernel ---------------------------------------
__global__ void __launch_bounds__(NT, 2)
speller_mega(const float* __restrict__ lis,
             const float* __restrict__ Wih0, const float* __restrict__ Whh0,
             const float* __restrict__ bih0, const float* __restrict__ bhh0,
             const float* __restrict__ Wih1, const float* __restrict__ Whh1,
             const float* __restrict__ bih1, const float* __restrict__ bhh1,
             const float* __restrict__ Wphi, const float* __restrict__ bphi,
             const float* __restrict__ Wpsi, const float* __restrict__ bpsi,
             const float* __restrict__ Wc,   const float* __restrict__ bc,
             float* __restrict__ preds, float* __restrict__ attns) {
    __shared__ float sm[128 * 33 + 32 * 33];   // 5280 floats, reused by every phase
    const int blk = blockIdx.x;
    const int nb = gridDim.x;
    const int gtid = blk * NT + threadIdx.x;
    const int gsz = nb * NT;

    unsigned gen_next = 0;
    if (threadIdx.x == 0) gen_next = atomicAdd(&g_barGen, 0u) + 1;

    // one-time psi (512 tasks) — no cross-task dependency
    for (int t = blk; t < 512; t += nb) psi_task(t, lis, Wpsi, bpsi, sm);

    // init x0 = [onehot(0), listener[:,0,:]] and zero LSTM states
    for (int i = gtid; i < BB * XD; i += gsz) {
        int b = i / XD, k = i - b * XD;
        float v = 0.f;
        if (k == 0) v = 1.f;
        else if (k >= VV) v = lis[(size_t)b * TL * DL + (k - VV)];
        g_x[i] = v;
    }
    for (int i = gtid; i < BB * HH; i += gsz) {
        g_h0[i] = 0.f; g_c0[i] = 0.f; g_h1[i] = 0.f; g_c1[i] = 0.f;
    }
    gsync(gen_next);

    for (int step = 0; step < NSTEP; step++) {
        // P1: gates0 (Wih0@x, Whh0@h0) + gates1's Whh1@h1_prev — 448 tasks
        for (int t = blk; t < 448; t += nb) {
            if (t < 320) {
                int tile = t & 15, slot = t >> 4;
                int k0 = slot * 128, k1 = min(XD, k0 + 128);
                gemm_task(Wih0, XD, G4, g_x, XD, tile * 128, k0, k1,
                          g_p0 + (size_t)slot * G4 * BB, sm);
            } else if (t < 384) {
                int t2 = t - 320; int tile = t2 & 15, slot = t2 >> 4;
                gemm_task(Whh0, HH, G4, g_h0, HH, tile * 128, slot * 128, slot * 128 + 128,
                          g_p0 + (size_t)(S_WIH0 + slot) * G4 * BB, sm);
            } else {
                int t3 = t - 384; int tile = t3 & 15, slot = t3 >> 4;
                gemm_task(Whh1, HH, G4, g_h1, HH, tile * 128, slot * 128, slot * 128 + 128,
                          g_p1 + (size_t)slot * G4 * BB, sm);
            }
        }
        gsync(gen_next);
        // P2: LSTM cell 0
        cell_phase(g_p0, S_P0, bih0, bhh0, g_h0, g_c0, nullptr);
        gsync(gen_next);
        // P3: gates1's Wih1@h0_new — 64 tasks
        for (int t = blk; t < 64; t += nb) {
            int tile = t & 15, slot = t >> 4;
            gemm_task(Wih1, HH, G4, g_h0, HH, tile * 128, slot * 128, slot * 128 + 128,
                      g_p1 + (size_t)(4 + slot) * G4 * BB, sm);
        }
        gsync(gen_next);
        // P4: LSTM cell 1 (also copies h1 into cat[:, :512])
        cell_phase(g_p1, S_P1, bih1, bhh1, g_h1, g_c1, g_cat);
        gsync(gen_next);
        // P5: attention (blocks 0..31) || logits h1-half (blocks 32..95)
        if (blk < 32) {
            attn_phase(blk, lis, Wphi, bphi,
                       attns + ((size_t)step * BB + blk) * TL, sm);
        } else if (blk < 96) {
            int t = blk - 32;
            int tile = t & 15, slot = t >> 4;
            gemm_task(Wc, CATD, VV, g_cat, CATD, tile * 128, slot * 128, slot * 128 + 128,
                      g_pl + (size_t)slot * LROWS * BB, sm);
        }
        gsync(gen_next);
        // P6: logits context-half (blocks 0..63)
        if (blk < 64) {
            int tile = blk & 15, slot = blk >> 4;
            gemm_task(Wc, CATD, VV, g_cat, CATD, tile * 128,
                      512 + slot * 128, 512 + slot * 128 + 128,
                      g_pl + (size_t)(4 + slot) * LROWS * BB, sm);
        }
        gsync(gen_next);
        // P7: log-softmax + feedback (blocks 0..31)
        if (blk < 32) lsm_phase(blk, bc, preds + (size_t)step * BB * VV, sm);
        gsync(gen_next);
    }
}

// ---------------- host launcher ----------------------------------------------
extern "C" void kernel_launch(void* const* d_in, const int* in_sizes, int n_in,
                              void* d_out, int out_size) {
    const float* lis  = (const float*)d_in[0];
    const float* Wih0 = (const float*)d_in[1];
    const float* Whh0 = (const float*)d_in[2];
    const float* bih0 = (const float*)d_in[3];
    const float* bhh0 = (const float*)d_in[4];
    const float* Wih1 = (const float*)d_in[5];
    const float* Whh1 = (const float*)d_in[6];
    const float* bih1 = (const float*)d_in[7];
    const float* bhh1 = (const float*)d_in[8];
    const float* Wphi = (const float*)d_in[9];
    const float* bphi = (const float*)d_in[10];
    const float* Wpsi = (const float*)d_in[11];
    const float* bpsi = (const float*)d_in[12];
    const float* Wc   = (const float*)d_in[13];
    const float* bc   = (const float*)d_in[14];

    float* preds = (float*)d_out;                      // [100,32,2000]
    float* attns = preds + (size_t)NSTEP * BB * VV;    // [100,32,256]

    int nsm = 0;
    cudaDeviceGetAttribute(&nsm, cudaDevAttrMultiProcessorCount, 0);
    int nb = nsm * 2;     // 2 blocks/SM, guaranteed co-resident via launch bounds

    speller_mega<<<nb, NT>>>(lis, Wih0, Whh0, bih0, bhh0,
                             Wih1, Whh1, bih1, bhh1,
                             Wphi, bphi, Wpsi, bpsi, Wc, bc,
                             preds, attns);
}